// round 8
// baseline (speedup 1.0000x reference)
#include <cuda_runtime.h>
#include <cuda_bf16.h>

#define BINS 10

// Zero-initialized at module load; the finalizing block resets them after use,
// so every graph replay (and the correctness run) starts from a clean state.
static __device__ float        g_cnt[BINS];
static __device__ float        g_sum[BINS];
static __device__ unsigned int g_ticket;

// One warp per row, 8 warps (256 threads) per block. Single fused kernel:
// per-row softmax-sum + CE loss + bin histogram, then last block finalizes.
__global__ __launch_bounds__(256) void ghm_fused(
    const float* __restrict__ pred,
    const int*   __restrict__ target,   // JAX int64 -> int32 (x64 disabled)
    float*       __restrict__ out,
    int B, int C)
{
    __shared__ float s_cnt[BINS];
    __shared__ float s_sum[BINS];
    __shared__ bool  s_last;
    if (threadIdx.x < BINS) { s_cnt[threadIdx.x] = 0.0f; s_sum[threadIdx.x] = 0.0f; }
    if (threadIdx.x == 0) s_last = false;
    __syncthreads();

    const int warp = threadIdx.x >> 5;
    const int lane = threadIdx.x & 31;
    const int row  = blockIdx.x * (blockDim.x >> 5) + warp;

    if (row < B) {
        const size_t base = (size_t)row * (size_t)C;
        const float4* __restrict__ p4 = (const float4*)(pred + base);
        const int n4 = C >> 2;                 // 250 for C=1000 (4000B row stride, 16B aligned)

        float s = 0.0f;
        // Chunks of 256 float4 per warp; all 8 loads issued before any MUFU work (MLP=8).
        for (int i0 = 0; i0 < n4; i0 += 256) {
            float4 v[8];
            #pragma unroll
            for (int k = 0; k < 8; ++k) {
                // Sentinel: exp(-1e30f) == 0, so masked lanes contribute nothing.
                v[k] = make_float4(-1e30f, -1e30f, -1e30f, -1e30f);
                const int idx = i0 + lane + (k << 5);
                if (idx < n4) v[k] = p4[idx];
            }
            #pragma unroll
            for (int k = 0; k < 8; ++k)
                s += __expf(v[k].x) + __expf(v[k].y) + __expf(v[k].z) + __expf(v[k].w);
        }
        // tail for C % 4 != 0 (not hit for C=1000)
        for (int j = (n4 << 2) + lane; j < C; j += 32) s += __expf(pred[base + j]);

        #pragma unroll
        for (int o = 16; o; o >>= 1) s += __shfl_xor_sync(0xffffffffu, s, o);

        if (lane == 0) {
            int t = target[row];
            t = t < 0 ? 0 : (t >= C ? C - 1 : t);  // crash-guard; rel_err would expose misuse
            const float tv = pred[base + (size_t)t];
            const float g = 1.0f - __expf(tv) / s;
            int b = (int)floorf(g * 10.0f);
            b = b < 0 ? 0 : (b > BINS - 1 ? BINS - 1 : b);
            const float loss = -tv + __logf(s + 1e-8f);
            atomicAdd(&s_cnt[b], 1.0f);
            atomicAdd(&s_sum[b], loss);
        }
    }

    __syncthreads();
    if (threadIdx.x < BINS) {
        const float c = s_cnt[threadIdx.x];
        if (c != 0.0f) {
            atomicAdd(&g_cnt[threadIdx.x], c);
            atomicAdd(&g_sum[threadIdx.x], s_sum[threadIdx.x]);
        }
    }

    // Last-block ticket: finalize + reset state for the next replay.
    __threadfence();
    __syncthreads();
    if (threadIdx.x == 0) {
        const unsigned int t = atomicAdd(&g_ticket, 1u);
        s_last = (t == gridDim.x - 1u);
    }
    __syncthreads();

    if (s_last && threadIdx.x == 0) {
        float n_nonempty = 0.0f;
        float tot = 0.0f;
        #pragma unroll
        for (int b = 0; b < BINS; ++b) {
            const float c = __ldcg(&g_cnt[b]);   // bypass L1: values live in L2 (atomics)
            const float l = __ldcg(&g_sum[b]);
            if (c > 0.0f) { n_nonempty += 1.0f; tot += l / c; }
        }
        out[0] = tot / fmaxf(n_nonempty, 1.0f);
        // Reset for next execution (deterministic across graph replays); L2-level
        // stores so the next replay's atomics/__ldcg observe them directly.
        #pragma unroll
        for (int b = 0; b < BINS; ++b) { __stcg(&g_cnt[b], 0.0f); __stcg(&g_sum[b], 0.0f); }
        __threadfence();
        __stcg(&g_ticket, 0u);
    }
}

extern "C" void kernel_launch(void* const* d_in, const int* in_sizes, int n_in,
                              void* d_out, int out_size) {
    const float* pred   = (const float*)d_in[0];
    const int*   target = (const int*)d_in[1];
    float*       out    = (float*)d_out;

    const int B = in_sizes[1];            // 65536 rows
    const int C = in_sizes[0] / B;        // 1000 classes

    const int warps_per_block = 8;        // 256 threads
    const int grid = (B + warps_per_block - 1) / warps_per_block;
    ghm_fused<<<grid, 256>>>(pred, target, out, B, C);
}

// round 9
// speedup vs baseline: 1.0661x; 1.0661x over previous
#include <cuda_runtime.h>
#include <cuda_bf16.h>

#define BINS 10

// Zero-initialized at module load; the finalizing block resets them after use,
// so every graph replay (and the correctness run) starts from a clean state.
static __device__ float        g_cnt[BINS];
static __device__ float        g_sum[BINS];
static __device__ unsigned int g_ticket;

// One warp per row, 8 warps (256 threads) per block, fused single kernel.
// __launch_bounds__(256, 8): cap registers at 32/thread so 8 blocks (64 warps)
// fit per SM — latency hiding via warps, not per-thread staging.
__global__ __launch_bounds__(256, 8) void ghm_fused(
    const float* __restrict__ pred,
    const int*   __restrict__ target,   // JAX int64 -> int32 (x64 disabled)
    float*       __restrict__ out,
    int B, int C)
{
    __shared__ float s_cnt[BINS];
    __shared__ float s_sum[BINS];
    __shared__ bool  s_last;
    if (threadIdx.x < BINS) { s_cnt[threadIdx.x] = 0.0f; s_sum[threadIdx.x] = 0.0f; }
    if (threadIdx.x == 0) s_last = false;
    __syncthreads();

    const int warp = threadIdx.x >> 5;
    const int lane = threadIdx.x & 31;
    const int row  = blockIdx.x * (blockDim.x >> 5) + warp;

    if (row < B) {
        const size_t base = (size_t)row * (size_t)C;

        // Lane 0 kicks off the scalar gathers early so their latency overlaps
        // the streaming loop below.
        int   t  = 0;
        float tv = 0.0f;
        if (lane == 0) {
            t = target[row];
            t = t < 0 ? 0 : (t >= C ? C - 1 : t);  // crash-guard; rel_err exposes misuse
            tv = pred[base + (size_t)t];
        }

        const float4* __restrict__ p4 = (const float4*)(pred + base);
        const int n4 = C >> 2;           // 250 for C=1000 (4000B row stride, 16B aligned)

        float s = 0.0f;
        #pragma unroll 4
        for (int i = lane; i < n4; i += 32) {
            float4 v = p4[i];
            s += __expf(v.x) + __expf(v.y) + __expf(v.z) + __expf(v.w);
        }
        // tail for C % 4 != 0 (not hit for C=1000)
        for (int j = (n4 << 2) + lane; j < C; j += 32) s += __expf(pred[base + j]);

        #pragma unroll
        for (int o = 16; o; o >>= 1) s += __shfl_xor_sync(0xffffffffu, s, o);

        if (lane == 0) {
            const float g = 1.0f - __expf(tv) / s;
            int b = (int)floorf(g * 10.0f);
            b = b < 0 ? 0 : (b > BINS - 1 ? BINS - 1 : b);
            const float loss = -tv + __logf(s + 1e-8f);
            atomicAdd(&s_cnt[b], 1.0f);
            atomicAdd(&s_sum[b], loss);
        }
    }

    __syncthreads();
    if (threadIdx.x < BINS) {
        const float c = s_cnt[threadIdx.x];
        if (c != 0.0f) {
            atomicAdd(&g_cnt[threadIdx.x], c);
            atomicAdd(&g_sum[threadIdx.x], s_sum[threadIdx.x]);
        }
    }

    // Last-block ticket: finalize + reset state for the next replay.
    __threadfence();
    __syncthreads();
    if (threadIdx.x == 0) {
        const unsigned int tk = atomicAdd(&g_ticket, 1u);
        s_last = (tk == gridDim.x - 1u);
    }
    __syncthreads();

    if (s_last && threadIdx.x == 0) {
        float n_nonempty = 0.0f;
        float tot = 0.0f;
        #pragma unroll
        for (int b = 0; b < BINS; ++b) {
            const float c = __ldcg(&g_cnt[b]);   // bypass L1: values live in L2 (atomics)
            const float l = __ldcg(&g_sum[b]);
            if (c > 0.0f) { n_nonempty += 1.0f; tot += l / c; }
        }
        out[0] = tot / fmaxf(n_nonempty, 1.0f);
        // Reset for next execution (deterministic across graph replays); L2-level
        // stores so the next replay's atomics/__ldcg observe them directly.
        #pragma unroll
        for (int b = 0; b < BINS; ++b) { __stcg(&g_cnt[b], 0.0f); __stcg(&g_sum[b], 0.0f); }
        __threadfence();
        __stcg(&g_ticket, 0u);
    }
}

extern "C" void kernel_launch(void* const* d_in, const int* in_sizes, int n_in,
                              void* d_out, int out_size) {
    const float* pred   = (const float*)d_in[0];
    const int*   target = (const int*)d_in[1];
    float*       out    = (float*)d_out;

    const int B = in_sizes[1];            // 65536 rows
    const int C = in_sizes[0] / B;        // 1000 classes

    const int warps_per_block = 8;        // 256 threads
    const int grid = (B + warps_per_block - 1) / warps_per_block;
    ghm_fused<<<grid, 256>>>(pred, target, out, B, C);
}